// round 1
// baseline (speedup 1.0000x reference)
#include <cuda_runtime.h>
#include <cstdint>

#define NMAX 100000
#define EMAX 1600000
#define HDIM 128
#define BN_EPS 1e-5f

// Static scratch (allocation-free rule): h buffer, agg buffer, scalar buffer.
__device__ float g_h[(size_t)NMAX * HDIM];    // current hidden state (in-place updated)
__device__ float g_agg[(size_t)NMAX * HDIM];  // aggregation target
__device__ float g_s[NMAX];                   // scalar scratch: deg-agg (L1), y (L4)

// ---------------------------------------------------------------------------
// zero kernels (reference globals directly; no pointers needed)
// ---------------------------------------------------------------------------
__global__ void zero_agg_kernel(int n4) {
    int i = blockIdx.x * blockDim.x + threadIdx.x;
    if (i < n4) ((float4*)g_agg)[i] = make_float4(0.f, 0.f, 0.f, 0.f);
}

__global__ void zero_s_kernel(int n) {
    int i = blockIdx.x * blockDim.x + threadIdx.x;
    if (i < n) g_s[i] = 0.f;
}

// ---------------------------------------------------------------------------
// Layer 1: scalar aggregation (x is [N,1]) + elementwise affine/BN/ReLU
// ---------------------------------------------------------------------------
__global__ void scatter_scalar_kernel(const int* __restrict__ src,
                                      const int* __restrict__ dst,
                                      const float* __restrict__ x, int e) {
    int g = blockIdx.x * blockDim.x + threadIdx.x;
    if (g < e) atomicAdd(&g_s[dst[g]], x[src[g]]);
}

__global__ void layer1_kernel(const float* __restrict__ x,
                              const float* __restrict__ Wl1,
                              const float* __restrict__ Wr1,
                              const float* __restrict__ b1,
                              const float* __restrict__ g1,
                              const float* __restrict__ be1,
                              const float* __restrict__ m1,
                              const float* __restrict__ v1, int n) {
    int g = blockIdx.x * blockDim.x + threadIdx.x;
    if (g < n * HDIM) {
        int i = g >> 7;
        int f = g & 127;
        float s = g1[f] * rsqrtf(v1[f] + BN_EPS);
        float pre = g_s[i] * Wl1[f] + x[i] * Wr1[f] + b1[f];
        float val = (pre - m1[f]) * s + be1[f];
        g_h[g] = fmaxf(val, 0.f);
    }
}

// ---------------------------------------------------------------------------
// Feature scatter: one warp per edge, float4 gather + vectorized f32 reduction
// ---------------------------------------------------------------------------
__global__ void scatter_feat_kernel(const int* __restrict__ src,
                                    const int* __restrict__ dst, int e) {
    int g = blockIdx.x * blockDim.x + threadIdx.x;
    int edge = g >> 5;
    int lane = g & 31;
    if (edge < e) {
        int s = src[edge];
        int d = dst[edge];
        float4 v = ((const float4*)(g_h + (size_t)s * HDIM))[lane];
        float* ap = g_agg + (size_t)d * HDIM + lane * 4;
        asm volatile("red.global.add.v4.f32 [%0], {%1,%2,%3,%4};"
                     :: "l"(ap), "f"(v.x), "f"(v.y), "f"(v.z), "f"(v.w)
                     : "memory");
    }
}

// ---------------------------------------------------------------------------
// Fused GEMM: h_new = relu(bn(agg @ Wl + h @ Wr + b))   (in-place into g_h)
// A = [agg_row | h_row] (K=256), W = [Wl ; Wr] (256 x 128), weights smem-resident.
// Block: 256 threads, 32 rows/tile, 4x4 register micro-tile per thread.
// ---------------------------------------------------------------------------
#define GEMM_SMEM_BYTES ((256 * 128 + 32 * 256 + 256) * 4)

__global__ void __launch_bounds__(256, 1)
gemm_bn_relu_kernel(const float* __restrict__ Wl, const float* __restrict__ Wr,
                    const float* __restrict__ bias,
                    const float* __restrict__ gam, const float* __restrict__ bet,
                    const float* __restrict__ mean, const float* __restrict__ var,
                    int n) {
    extern __shared__ float sm[];
    float* sW = sm;                 // 256 x 128
    float* sA = sm + 256 * 128;     // 32 x 256
    float* sScale = sA + 32 * 256;  // 128
    float* sBias = sScale + 128;    // 128

    int tid = threadIdx.x;

    // Load combined weight matrix into smem (float4)
    for (int v = tid; v < (256 * 128) / 4; v += 256) {
        int k = v >> 5;       // 0..255
        int c4 = v & 31;      // float4 column
        float4 w;
        if (k < 128) w = ((const float4*)Wl)[k * 32 + c4];
        else         w = ((const float4*)Wr)[(k - 128) * 32 + c4];
        ((float4*)sW)[v] = w;
    }
    if (tid < 128) {
        float s = gam[tid] * rsqrtf(var[tid] + BN_EPS);
        sScale[tid] = s;
        sBias[tid] = (bias[tid] - mean[tid]) * s + bet[tid];
    }
    __syncthreads();

    int c0 = (tid & 31) * 4;   // output column group
    int r0 = (tid >> 5) * 4;   // row group within tile
    int ntiles = (n + 31) / 32;

    for (int tile = blockIdx.x; tile < ntiles; tile += gridDim.x) {
        int rowBase = tile * 32;

        // Load A tile (32 rows x 256): [agg | h]
        for (int v = tid; v < 32 * 64; v += 256) {
            int r = v >> 6;
            int c4 = v & 63;
            int row = rowBase + r;
            float4 a = make_float4(0.f, 0.f, 0.f, 0.f);
            if (row < n) {
                if (c4 < 32) a = ((const float4*)g_agg)[(size_t)row * 32 + c4];
                else         a = ((const float4*)g_h)[(size_t)row * 32 + (c4 - 32)];
            }
            ((float4*)sA)[v] = a;
        }
        __syncthreads();

        float acc[4][4];
        #pragma unroll
        for (int i = 0; i < 4; i++)
            #pragma unroll
            for (int j = 0; j < 4; j++) acc[i][j] = 0.f;

        #pragma unroll 4
        for (int k = 0; k < 256; k += 4) {
            float a[4][4], w[4][4];
            #pragma unroll
            for (int r = 0; r < 4; r++)
                *(float4*)&a[r][0] = *(const float4*)&sA[(r0 + r) * 256 + k];
            #pragma unroll
            for (int j = 0; j < 4; j++)
                *(float4*)&w[j][0] = *(const float4*)&sW[(k + j) * 128 + c0];
            #pragma unroll
            for (int r = 0; r < 4; r++)
                #pragma unroll
                for (int j = 0; j < 4; j++)
                    #pragma unroll
                    for (int c = 0; c < 4; c++)
                        acc[r][c] += a[r][j] * w[j][c];
        }
        __syncthreads();  // sA consumed; safe to overwrite next iteration

        // Epilogue: BN + ReLU, in-place into g_h (row owned exclusively by this tile)
        #pragma unroll
        for (int i = 0; i < 4; i++) {
            int row = rowBase + r0 + i;
            if (row < n) {
                float4 o;
                o.x = fmaxf(acc[i][0] * sScale[c0 + 0] + sBias[c0 + 0], 0.f);
                o.y = fmaxf(acc[i][1] * sScale[c0 + 1] + sBias[c0 + 1], 0.f);
                o.z = fmaxf(acc[i][2] * sScale[c0 + 2] + sBias[c0 + 2], 0.f);
                o.w = fmaxf(acc[i][3] * sScale[c0 + 3] + sBias[c0 + 3], 0.f);
                ((float4*)g_h)[(size_t)row * 32 + (c0 >> 2)] = o;
            }
        }
    }
}

// ---------------------------------------------------------------------------
// Layer 4 (commuted): y = h3 @ Wl4 first (N x 1), out_base = h3 @ Wr4 + b4.
// Then scalar scatter of y into out. One warp per node.
// ---------------------------------------------------------------------------
__global__ void layer4_node_kernel(const float* __restrict__ Wl4,
                                   const float* __restrict__ Wr4,
                                   const float* __restrict__ b4,
                                   float* __restrict__ out, int n) {
    int g = blockIdx.x * blockDim.x + threadIdx.x;
    int i = g >> 5;
    int lane = g & 31;
    if (i < n) {
        float4 hv = ((const float4*)(g_h + (size_t)i * HDIM))[lane];
        float4 wl = ((const float4*)Wl4)[lane];
        float4 wr = ((const float4*)Wr4)[lane];
        float yv = hv.x * wl.x + hv.y * wl.y + hv.z * wl.z + hv.w * wl.w;
        float zv = hv.x * wr.x + hv.y * wr.y + hv.z * wr.z + hv.w * wr.w;
        #pragma unroll
        for (int o = 16; o > 0; o >>= 1) {
            yv += __shfl_xor_sync(0xFFFFFFFFu, yv, o);
            zv += __shfl_xor_sync(0xFFFFFFFFu, zv, o);
        }
        if (lane == 0) {
            g_s[i] = yv;
            out[i] = zv + b4[0];
        }
    }
}

__global__ void layer4_scatter_kernel(const int* __restrict__ src,
                                      const int* __restrict__ dst,
                                      float* __restrict__ out, int e) {
    int g = blockIdx.x * blockDim.x + threadIdx.x;
    if (g < e) atomicAdd(&out[dst[g]], g_s[src[g]]);
}

// ---------------------------------------------------------------------------
// Launch
// ---------------------------------------------------------------------------
extern "C" void kernel_launch(void* const* d_in, const int* in_sizes, int n_in,
                              void* d_out, int out_size) {
    const float* x  = (const float*)d_in[0];
    const int*   ei = (const int*)d_in[1];
    const float* Wl1 = (const float*)d_in[2];
    const float* Wr1 = (const float*)d_in[3];
    const float* b1  = (const float*)d_in[4];
    const float* Wl2 = (const float*)d_in[5];
    const float* Wr2 = (const float*)d_in[6];
    const float* b2  = (const float*)d_in[7];
    const float* Wl3 = (const float*)d_in[8];
    const float* Wr3 = (const float*)d_in[9];
    const float* b3  = (const float*)d_in[10];
    const float* Wl4 = (const float*)d_in[11];
    const float* Wr4 = (const float*)d_in[12];
    const float* b4  = (const float*)d_in[13];
    const float* g1  = (const float*)d_in[14];
    const float* be1 = (const float*)d_in[15];
    const float* m1  = (const float*)d_in[16];
    const float* v1  = (const float*)d_in[17];
    const float* g2  = (const float*)d_in[18];
    const float* be2 = (const float*)d_in[19];
    const float* m2  = (const float*)d_in[20];
    const float* v2  = (const float*)d_in[21];
    const float* g3  = (const float*)d_in[22];
    const float* be3 = (const float*)d_in[23];
    const float* m3  = (const float*)d_in[24];
    const float* v3  = (const float*)d_in[25];

    int n = in_sizes[0];          // x is [N,1]
    int e = in_sizes[1] / 2;      // edge_index is [2,E]
    const int* src = ei;
    const int* dst = ei + e;
    float* out = (float*)d_out;

    cudaFuncSetAttribute(gemm_bn_relu_kernel,
                         cudaFuncAttributeMaxDynamicSharedMemorySize,
                         GEMM_SMEM_BYTES);

    int nH4 = (n * HDIM) / 4;
    int ntiles = (n + 31) / 32;
    int gemmGrid = ntiles < 625 ? ntiles : 625;

    // --- Layer 1 (scalar aggregation) ---
    zero_s_kernel<<<(n + 255) / 256, 256>>>(n);
    scatter_scalar_kernel<<<(e + 255) / 256, 256>>>(src, dst, x, e);
    layer1_kernel<<<(n * HDIM + 255) / 256, 256>>>(x, Wl1, Wr1, b1, g1, be1, m1, v1, n);

    // --- Layer 2 ---
    zero_agg_kernel<<<(nH4 + 255) / 256, 256>>>(nH4);
    scatter_feat_kernel<<<(e * 32 + 255) / 256, 256>>>(src, dst, e);
    gemm_bn_relu_kernel<<<gemmGrid, 256, GEMM_SMEM_BYTES>>>(Wl2, Wr2, b2, g2, be2, m2, v2, n);

    // --- Layer 3 ---
    zero_agg_kernel<<<(nH4 + 255) / 256, 256>>>(nH4);
    scatter_feat_kernel<<<(e * 32 + 255) / 256, 256>>>(src, dst, e);
    gemm_bn_relu_kernel<<<gemmGrid, 256, GEMM_SMEM_BYTES>>>(Wl3, Wr3, b3, g3, be3, m3, v3, n);

    // --- Layer 4 (projection commuted before aggregation: E x 1 scatter) ---
    layer4_node_kernel<<<(n * 32 + 255) / 256, 256>>>(Wl4, Wr4, b4, out, n);
    layer4_scatter_kernel<<<(e + 255) / 256, 256>>>(src, dst, out, e);
}

// round 2
// speedup vs baseline: 1.4224x; 1.4224x over previous
#include <cuda_runtime.h>
#include <cstdint>

#define NMAX 100000
#define EMAX 1600000
#define HDIM 128
#define BN_EPS 1e-5f

// Static scratch (allocation-free rule)
__device__ float g_h[(size_t)NMAX * HDIM];    // hidden state (updated in place per layer)
__device__ float g_agg[(size_t)NMAX * HDIM];  // feature aggregation target
__device__ float g_s[NMAX];                   // scalar scratch: deg-agg (L1), y (L4)
__device__ int   g_deg[NMAX];                 // degree histogram
__device__ int   g_rowptr[NMAX + 1];          // CSR row pointers
__device__ int   g_cursor[NMAX];              // CSR fill cursors
__device__ int   g_csr[EMAX];                 // CSR src lists (grouped by dst)

// ---------------------------------------------------------------------------
// CSR build: histogram -> prefix scan -> fill
// ---------------------------------------------------------------------------
__global__ void zero_deg_kernel(int n) {
    int i = blockIdx.x * blockDim.x + threadIdx.x;
    if (i < n) g_deg[i] = 0;
}

__global__ void count_kernel(const int* __restrict__ dst, int e) {
    int i = blockIdx.x * blockDim.x + threadIdx.x;
    if (i < e) atomicAdd(&g_deg[dst[i]], 1);
}

// Single-block chunked exclusive scan (1024 threads, warp-shuffle based).
__global__ void scan_kernel(int n) {
    __shared__ int warpsum[32];
    __shared__ int carry;
    int tid = threadIdx.x;
    int lane = tid & 31;
    int w = tid >> 5;
    if (tid == 0) carry = 0;
    __syncthreads();
    for (int base = 0; base < n; base += 1024) {
        int i = base + tid;
        int v = (i < n) ? g_deg[i] : 0;
        int incl = v;
        #pragma unroll
        for (int o = 1; o < 32; o <<= 1) {
            int t = __shfl_up_sync(0xFFFFFFFFu, incl, o);
            if (lane >= o) incl += t;
        }
        if (lane == 31) warpsum[w] = incl;
        __syncthreads();
        if (w == 0) {
            int s = warpsum[lane];
            #pragma unroll
            for (int o = 1; o < 32; o <<= 1) {
                int t = __shfl_up_sync(0xFFFFFFFFu, s, o);
                if (lane >= o) s += t;
            }
            warpsum[lane] = s;
        }
        __syncthreads();
        int woff = (w > 0) ? warpsum[w - 1] : 0;
        int excl = carry + woff + incl - v;
        if (i < n) {
            g_rowptr[i] = excl;
            g_cursor[i] = excl;
        }
        __syncthreads();
        if (tid == 0) carry += warpsum[31];
        __syncthreads();
    }
    if (threadIdx.x == 0) g_rowptr[n] = carry;
}

__global__ void fill_kernel(const int* __restrict__ src,
                            const int* __restrict__ dst, int e) {
    int i = blockIdx.x * blockDim.x + threadIdx.x;
    if (i < e) {
        int pos = atomicAdd(&g_cursor[dst[i]], 1);
        g_csr[pos] = src[i];
    }
}

// ---------------------------------------------------------------------------
// Layer 1: scalar gather (x is [N,1]) + elementwise affine/BN/ReLU
// ---------------------------------------------------------------------------
__global__ void gather_scalar_x_kernel(const float* __restrict__ x, int n) {
    int i = blockIdx.x * blockDim.x + threadIdx.x;
    if (i < n) {
        int b = g_rowptr[i], eend = g_rowptr[i + 1];
        float acc = 0.f;
        for (int j = b; j < eend; j++) acc += x[g_csr[j]];
        g_s[i] = acc;
    }
}

__global__ void layer1_kernel(const float* __restrict__ x,
                              const float* __restrict__ Wl1,
                              const float* __restrict__ Wr1,
                              const float* __restrict__ b1,
                              const float* __restrict__ g1,
                              const float* __restrict__ be1,
                              const float* __restrict__ m1,
                              const float* __restrict__ v1, int n) {
    int g = blockIdx.x * blockDim.x + threadIdx.x;
    if (g < n * HDIM) {
        int i = g >> 7;
        int f = g & 127;
        float s = g1[f] * rsqrtf(v1[f] + BN_EPS);
        float pre = g_s[i] * Wl1[f] + x[i] * Wr1[f] + b1[f];
        float val = (pre - m1[f]) * s + be1[f];
        g_h[g] = fmaxf(val, 0.f);
    }
}

// ---------------------------------------------------------------------------
// Feature gather: one warp per dst node, register accumulation, no atomics.
// ---------------------------------------------------------------------------
__global__ void gather_feat_kernel(int n) {
    int g = blockIdx.x * blockDim.x + threadIdx.x;
    int node = g >> 5;
    int lane = g & 31;
    if (node >= n) return;
    int b = g_rowptr[node], eend = g_rowptr[node + 1];
    float4 acc = make_float4(0.f, 0.f, 0.f, 0.f);
    const float4* hp = (const float4*)g_h;
    int j = b;
    for (; j + 4 <= eend; j += 4) {
        int s0 = g_csr[j], s1 = g_csr[j + 1], s2 = g_csr[j + 2], s3 = g_csr[j + 3];
        float4 v0 = hp[(size_t)s0 * 32 + lane];
        float4 v1 = hp[(size_t)s1 * 32 + lane];
        float4 v2 = hp[(size_t)s2 * 32 + lane];
        float4 v3 = hp[(size_t)s3 * 32 + lane];
        acc.x += v0.x + v1.x + v2.x + v3.x;
        acc.y += v0.y + v1.y + v2.y + v3.y;
        acc.z += v0.z + v1.z + v2.z + v3.z;
        acc.w += v0.w + v1.w + v2.w + v3.w;
    }
    for (; j < eend; j++) {
        int s0 = g_csr[j];
        float4 v0 = hp[(size_t)s0 * 32 + lane];
        acc.x += v0.x; acc.y += v0.y; acc.z += v0.z; acc.w += v0.w;
    }
    ((float4*)g_agg)[(size_t)node * 32 + lane] = acc;
}

// ---------------------------------------------------------------------------
// Fused GEMM: h_new = relu(bn(agg @ Wl + h @ Wr + b))   (in-place into g_h)
// A = [agg_row | h_row] (K=256), W = [Wl ; Wr] (256 x 128), weights smem-resident.
// 256 threads, 64 rows/tile, 8x4 register micro-tile per thread. Persistent grid.
// ---------------------------------------------------------------------------
#define TROWS 64
#define GEMM_SMEM_BYTES ((256 * 128 + TROWS * 256 + 256) * 4)

__global__ void __launch_bounds__(256, 1)
gemm_bn_relu_kernel(const float* __restrict__ Wl, const float* __restrict__ Wr,
                    const float* __restrict__ bias,
                    const float* __restrict__ gam, const float* __restrict__ bet,
                    const float* __restrict__ mean, const float* __restrict__ var,
                    int n) {
    extern __shared__ float sm[];
    float* sW = sm;                      // 256 x 128
    float* sA = sm + 256 * 128;          // TROWS x 256
    float* sScale = sA + TROWS * 256;    // 128
    float* sBias = sScale + 128;         // 128

    int tid = threadIdx.x;

    for (int v = tid; v < (256 * 128) / 4; v += 256) {
        int k = v >> 5;
        int c4 = v & 31;
        float4 w;
        if (k < 128) w = ((const float4*)Wl)[k * 32 + c4];
        else         w = ((const float4*)Wr)[(k - 128) * 32 + c4];
        ((float4*)sW)[v] = w;
    }
    if (tid < 128) {
        float s = gam[tid] * rsqrtf(var[tid] + BN_EPS);
        sScale[tid] = s;
        sBias[tid] = (bias[tid] - mean[tid]) * s + bet[tid];
    }
    __syncthreads();

    int c0 = (tid & 31) * 4;   // output column group
    int r0 = (tid >> 5) * 8;   // row group within tile (8 warps x 8 rows)
    int ntiles = (n + TROWS - 1) / TROWS;

    for (int tile = blockIdx.x; tile < ntiles; tile += gridDim.x) {
        int rowBase = tile * TROWS;

        // Load A tile (TROWS x 256): [agg | h]
        for (int v = tid; v < TROWS * 64; v += 256) {
            int r = v >> 6;
            int c4 = v & 63;
            int row = rowBase + r;
            float4 a = make_float4(0.f, 0.f, 0.f, 0.f);
            if (row < n) {
                if (c4 < 32) a = ((const float4*)g_agg)[(size_t)row * 32 + c4];
                else         a = ((const float4*)g_h)[(size_t)row * 32 + (c4 - 32)];
            }
            ((float4*)sA)[v] = a;
        }
        __syncthreads();

        float acc[8][4];
        #pragma unroll
        for (int i = 0; i < 8; i++)
            #pragma unroll
            for (int j = 0; j < 4; j++) acc[i][j] = 0.f;

        #pragma unroll 2
        for (int k = 0; k < 256; k += 4) {
            float a[8][4], w[4][4];
            #pragma unroll
            for (int r = 0; r < 8; r++)
                *(float4*)&a[r][0] = *(const float4*)&sA[(r0 + r) * 256 + k];
            #pragma unroll
            for (int j = 0; j < 4; j++)
                *(float4*)&w[j][0] = *(const float4*)&sW[(k + j) * 128 + c0];
            #pragma unroll
            for (int r = 0; r < 8; r++)
                #pragma unroll
                for (int j = 0; j < 4; j++)
                    #pragma unroll
                    for (int c = 0; c < 4; c++)
                        acc[r][c] += a[r][j] * w[j][c];
        }
        __syncthreads();

        #pragma unroll
        for (int i = 0; i < 8; i++) {
            int row = rowBase + r0 + i;
            if (row < n) {
                float4 o;
                o.x = fmaxf(acc[i][0] * sScale[c0 + 0] + sBias[c0 + 0], 0.f);
                o.y = fmaxf(acc[i][1] * sScale[c0 + 1] + sBias[c0 + 1], 0.f);
                o.z = fmaxf(acc[i][2] * sScale[c0 + 2] + sBias[c0 + 2], 0.f);
                o.w = fmaxf(acc[i][3] * sScale[c0 + 3] + sBias[c0 + 3], 0.f);
                ((float4*)g_h)[(size_t)row * 32 + (c0 >> 2)] = o;
            }
        }
    }
}

// ---------------------------------------------------------------------------
// Layer 4 (commuted): y = h3 @ Wl4 (N x 1), out_base = h3 @ Wr4 + b4;
// then out[i] = out_base[i] + sum_{j in N(i)} y[src_j]  (CSR gather, no atomics)
// ---------------------------------------------------------------------------
__global__ void layer4_node_kernel(const float* __restrict__ Wl4,
                                   const float* __restrict__ Wr4,
                                   const float* __restrict__ b4,
                                   float* __restrict__ out, int n) {
    int g = blockIdx.x * blockDim.x + threadIdx.x;
    int i = g >> 5;
    int lane = g & 31;
    if (i < n) {
        float4 hv = ((const float4*)(g_h + (size_t)i * HDIM))[lane];
        float4 wl = ((const float4*)Wl4)[lane];
        float4 wr = ((const float4*)Wr4)[lane];
        float yv = hv.x * wl.x + hv.y * wl.y + hv.z * wl.z + hv.w * wl.w;
        float zv = hv.x * wr.x + hv.y * wr.y + hv.z * wr.z + hv.w * wr.w;
        #pragma unroll
        for (int o = 16; o > 0; o >>= 1) {
            yv += __shfl_xor_sync(0xFFFFFFFFu, yv, o);
            zv += __shfl_xor_sync(0xFFFFFFFFu, zv, o);
        }
        if (lane == 0) {
            g_s[i] = yv;
            out[i] = zv + b4[0];
        }
    }
}

__global__ void layer4_gather_kernel(float* __restrict__ out, int n) {
    int i = blockIdx.x * blockDim.x + threadIdx.x;
    if (i < n) {
        int b = g_rowptr[i], eend = g_rowptr[i + 1];
        float acc = 0.f;
        for (int j = b; j < eend; j++) acc += g_s[g_csr[j]];
        out[i] += acc;
    }
}

// ---------------------------------------------------------------------------
// Launch
// ---------------------------------------------------------------------------
extern "C" void kernel_launch(void* const* d_in, const int* in_sizes, int n_in,
                              void* d_out, int out_size) {
    const float* x  = (const float*)d_in[0];
    const int*   ei = (const int*)d_in[1];
    const float* Wl1 = (const float*)d_in[2];
    const float* Wr1 = (const float*)d_in[3];
    const float* b1  = (const float*)d_in[4];
    const float* Wl2 = (const float*)d_in[5];
    const float* Wr2 = (const float*)d_in[6];
    const float* b2  = (const float*)d_in[7];
    const float* Wl3 = (const float*)d_in[8];
    const float* Wr3 = (const float*)d_in[9];
    const float* b3  = (const float*)d_in[10];
    const float* Wl4 = (const float*)d_in[11];
    const float* Wr4 = (const float*)d_in[12];
    const float* b4  = (const float*)d_in[13];
    const float* g1  = (const float*)d_in[14];
    const float* be1 = (const float*)d_in[15];
    const float* m1  = (const float*)d_in[16];
    const float* v1  = (const float*)d_in[17];
    const float* g2  = (const float*)d_in[18];
    const float* be2 = (const float*)d_in[19];
    const float* m2  = (const float*)d_in[20];
    const float* v2  = (const float*)d_in[21];
    const float* g3  = (const float*)d_in[22];
    const float* be3 = (const float*)d_in[23];
    const float* m3  = (const float*)d_in[24];
    const float* v3  = (const float*)d_in[25];

    int n = in_sizes[0];          // x is [N,1]
    int e = in_sizes[1] / 2;      // edge_index is [2,E]
    const int* src = ei;
    const int* dst = ei + e;
    float* out = (float*)d_out;

    cudaFuncSetAttribute(gemm_bn_relu_kernel,
                         cudaFuncAttributeMaxDynamicSharedMemorySize,
                         GEMM_SMEM_BYTES);

    // --- CSR build (dst-grouped src lists) ---
    zero_deg_kernel<<<(n + 255) / 256, 256>>>(n);
    count_kernel<<<(e + 255) / 256, 256>>>(dst, e);
    scan_kernel<<<1, 1024>>>(n);
    fill_kernel<<<(e + 255) / 256, 256>>>(src, dst, e);

    // --- Layer 1 (scalar gather) ---
    gather_scalar_x_kernel<<<(n + 255) / 256, 256>>>(x, n);
    layer1_kernel<<<(n * HDIM + 255) / 256, 256>>>(x, Wl1, Wr1, b1, g1, be1, m1, v1, n);

    // --- Layer 2 ---
    gather_feat_kernel<<<(n * 32 + 255) / 256, 256>>>(n);
    gemm_bn_relu_kernel<<<148, 256, GEMM_SMEM_BYTES>>>(Wl2, Wr2, b2, g2, be2, m2, v2, n);

    // --- Layer 3 ---
    gather_feat_kernel<<<(n * 32 + 255) / 256, 256>>>(n);
    gemm_bn_relu_kernel<<<148, 256, GEMM_SMEM_BYTES>>>(Wl3, Wr3, b3, g3, be3, m3, v3, n);

    // --- Layer 4 (projection commuted before aggregation: scalar gather) ---
    layer4_node_kernel<<<(n * 32 + 255) / 256, 256>>>(Wl4, Wr4, b4, out, n);
    layer4_gather_kernel<<<(n + 255) / 256, 256>>>(out, n);
}

// round 4
// speedup vs baseline: 1.8103x; 1.2727x over previous
#include <cuda_runtime.h>
#include <cuda_bf16.h>
#include <cstdint>

#define NMAX 100000
#define EMAX 1600000
#define HDIM 128
#define BN_EPS 1e-5f
#define LDA 264   // padded bf16 leading dim (conflict-free ldmatrix / LDS)
#define LDB 264

// ============================================================================
// Static scratch
// ============================================================================
__device__ float g_h[(size_t)NMAX * HDIM];
__device__ float g_agg[(size_t)NMAX * HDIM];
__device__ float g_s[NMAX];
__device__ int   g_deg[NMAX];
__device__ int   g_rowptr[NMAX + 1];
__device__ int   g_cursor[NMAX];
__device__ int   g_csr[EMAX];
// Pre-split transposed weights: [layer][part hi/lo][n=0..127][k padded to 264]
__device__ __nv_bfloat16 g_Bw[2][2][128][LDB];

// ============================================================================
// Helpers
// ============================================================================
__device__ __forceinline__ uint32_t smem_to_u32(const void* p) {
    uint32_t a;
    asm("{ .reg .u64 t; cvta.to.shared.u64 t, %1; cvt.u32.u64 %0, t; }"
        : "=r"(a) : "l"(p));
    return a;
}

__device__ __forceinline__ void ldmatrix_x4(uint32_t* r, uint32_t addr) {
    asm volatile("ldmatrix.sync.aligned.m8n8.x4.shared.b16 {%0,%1,%2,%3}, [%4];"
                 : "=r"(r[0]), "=r"(r[1]), "=r"(r[2]), "=r"(r[3]) : "r"(addr));
}

__device__ __forceinline__ void mma_bf16(float* c, const uint32_t* a, const uint32_t* b) {
    asm volatile(
        "mma.sync.aligned.m16n8k16.row.col.f32.bf16.bf16.f32 "
        "{%0,%1,%2,%3}, {%4,%5,%6,%7}, {%8,%9}, {%0,%1,%2,%3};"
        : "+f"(c[0]), "+f"(c[1]), "+f"(c[2]), "+f"(c[3])
        : "r"(a[0]), "r"(a[1]), "r"(a[2]), "r"(a[3]), "r"(b[0]), "r"(b[1]));
}

__device__ __forceinline__ unsigned long long split4(float4 v,
                                                    unsigned long long* lo_out) {
    __nv_bfloat16 h0 = __float2bfloat16(v.x);
    __nv_bfloat16 h1 = __float2bfloat16(v.y);
    __nv_bfloat16 h2 = __float2bfloat16(v.z);
    __nv_bfloat16 h3 = __float2bfloat16(v.w);
    __nv_bfloat16 l0 = __float2bfloat16(v.x - __bfloat162float(h0));
    __nv_bfloat16 l1 = __float2bfloat16(v.y - __bfloat162float(h1));
    __nv_bfloat16 l2 = __float2bfloat16(v.z - __bfloat162float(h2));
    __nv_bfloat16 l3 = __float2bfloat16(v.w - __bfloat162float(h3));
    *lo_out = (unsigned long long)__bfloat16_as_ushort(l0) |
              ((unsigned long long)__bfloat16_as_ushort(l1) << 16) |
              ((unsigned long long)__bfloat16_as_ushort(l2) << 32) |
              ((unsigned long long)__bfloat16_as_ushort(l3) << 48);
    return (unsigned long long)__bfloat16_as_ushort(h0) |
           ((unsigned long long)__bfloat16_as_ushort(h1) << 16) |
           ((unsigned long long)__bfloat16_as_ushort(h2) << 32) |
           ((unsigned long long)__bfloat16_as_ushort(h3) << 48);
}

// ============================================================================
// CSR build
// ============================================================================
__global__ void zero_deg_kernel(int n) {
    int i = blockIdx.x * blockDim.x + threadIdx.x;
    if (i < n) g_deg[i] = 0;
}

__global__ void count_kernel(const int* __restrict__ dst, int e) {
    int i = blockIdx.x * blockDim.x + threadIdx.x;
    if (i < e) atomicAdd(&g_deg[dst[i]], 1);
}

__global__ void scan_kernel(int n) {
    __shared__ int warpsum[32];
    __shared__ int carry;
    int tid = threadIdx.x;
    int lane = tid & 31;
    int w = tid >> 5;
    if (tid == 0) carry = 0;
    __syncthreads();
    for (int base = 0; base < n; base += 1024) {
        int i = base + tid;
        int v = (i < n) ? g_deg[i] : 0;
        int incl = v;
        #pragma unroll
        for (int o = 1; o < 32; o <<= 1) {
            int t = __shfl_up_sync(0xFFFFFFFFu, incl, o);
            if (lane >= o) incl += t;
        }
        if (lane == 31) warpsum[w] = incl;
        __syncthreads();
        if (w == 0) {
            int s = warpsum[lane];
            #pragma unroll
            for (int o = 1; o < 32; o <<= 1) {
                int t = __shfl_up_sync(0xFFFFFFFFu, s, o);
                if (lane >= o) s += t;
            }
            warpsum[lane] = s;
        }
        __syncthreads();
        int woff = (w > 0) ? warpsum[w - 1] : 0;
        int excl = carry + woff + incl - v;
        if (i < n) {
            g_rowptr[i] = excl;
            g_cursor[i] = excl;
        }
        __syncthreads();
        if (tid == 0) carry += warpsum[31];
        __syncthreads();
    }
    if (threadIdx.x == 0) g_rowptr[n] = carry;
}

__global__ void fill_kernel(const int* __restrict__ src,
                            const int* __restrict__ dst, int e) {
    int i = blockIdx.x * blockDim.x + threadIdx.x;
    if (i < e) {
        int pos = atomicAdd(&g_cursor[dst[i]], 1);
        g_csr[pos] = src[i];
    }
}

// ============================================================================
// Weight prep: transpose [k][n] -> [n][k], bf16 hi/lo split, padded rows
// ============================================================================
__global__ void prep_weights_kernel(const float* __restrict__ Wl2,
                                    const float* __restrict__ Wr2,
                                    const float* __restrict__ Wl3,
                                    const float* __restrict__ Wr3) {
    int t = blockIdx.x * blockDim.x + threadIdx.x;
    if (t >= 2 * 128 * 64) return;
    int layer = t >> 13;
    int rem = t & 8191;
    int nrow = rem >> 6;
    int kg = rem & 63;
    int k0 = kg * 4;
    const float* Wl = layer ? Wl3 : Wl2;
    const float* Wr = layer ? Wr3 : Wr2;
    float4 v;
    v.x = (k0 + 0 < 128) ? Wl[(k0 + 0) * 128 + nrow] : Wr[(k0 + 0 - 128) * 128 + nrow];
    v.y = (k0 + 1 < 128) ? Wl[(k0 + 1) * 128 + nrow] : Wr[(k0 + 1 - 128) * 128 + nrow];
    v.z = (k0 + 2 < 128) ? Wl[(k0 + 2) * 128 + nrow] : Wr[(k0 + 2 - 128) * 128 + nrow];
    v.w = (k0 + 3 < 128) ? Wl[(k0 + 3) * 128 + nrow] : Wr[(k0 + 3 - 128) * 128 + nrow];
    unsigned long long lo;
    unsigned long long hi = split4(v, &lo);
    *(unsigned long long*)&g_Bw[layer][0][nrow][k0] = hi;
    *(unsigned long long*)&g_Bw[layer][1][nrow][k0] = lo;
}

// ============================================================================
// Layer 1
// ============================================================================
__global__ void gather_scalar_x_kernel(const float* __restrict__ x, int n) {
    int i = blockIdx.x * blockDim.x + threadIdx.x;
    if (i < n) {
        int b = g_rowptr[i], eend = g_rowptr[i + 1];
        float acc = 0.f;
        for (int j = b; j < eend; j++) acc += x[g_csr[j]];
        g_s[i] = acc;
    }
}

__global__ void layer1_kernel(const float* __restrict__ x,
                              const float* __restrict__ Wl1,
                              const float* __restrict__ Wr1,
                              const float* __restrict__ b1,
                              const float* __restrict__ g1,
                              const float* __restrict__ be1,
                              const float* __restrict__ m1,
                              const float* __restrict__ v1, int n) {
    int g = blockIdx.x * blockDim.x + threadIdx.x;
    if (g < n * HDIM) {
        int i = g >> 7;
        int f = g & 127;
        float s = g1[f] * rsqrtf(v1[f] + BN_EPS);
        float pre = g_s[i] * Wl1[f] + x[i] * Wr1[f] + b1[f];
        float val = (pre - m1[f]) * s + be1[f];
        g_h[g] = fmaxf(val, 0.f);
    }
}

// ============================================================================
// Feature gather: one warp per dst node
// ============================================================================
__global__ void gather_feat_kernel(int n) {
    int g = blockIdx.x * blockDim.x + threadIdx.x;
    int node = g >> 5;
    int lane = g & 31;
    if (node >= n) return;
    int b = g_rowptr[node], eend = g_rowptr[node + 1];
    float4 acc = make_float4(0.f, 0.f, 0.f, 0.f);
    const float4* hp = (const float4*)g_h;
    int j = b;
    for (; j + 4 <= eend; j += 4) {
        int s0 = g_csr[j], s1 = g_csr[j + 1], s2 = g_csr[j + 2], s3 = g_csr[j + 3];
        float4 v0 = hp[(size_t)s0 * 32 + lane];
        float4 v1 = hp[(size_t)s1 * 32 + lane];
        float4 v2 = hp[(size_t)s2 * 32 + lane];
        float4 v3 = hp[(size_t)s3 * 32 + lane];
        acc.x += v0.x + v1.x + v2.x + v3.x;
        acc.y += v0.y + v1.y + v2.y + v3.y;
        acc.z += v0.z + v1.z + v2.z + v3.z;
        acc.w += v0.w + v1.w + v2.w + v3.w;
    }
    for (; j < eend; j++) {
        int s0 = g_csr[j];
        float4 v0 = hp[(size_t)s0 * 32 + lane];
        acc.x += v0.x; acc.y += v0.y; acc.z += v0.z; acc.w += v0.w;
    }
    ((float4*)g_agg)[(size_t)node * 32 + lane] = acc;
}

// ============================================================================
// mma.sync GEMM: h_new = relu(bn([agg|h] @ [Wl;Wr] + b)), split-bf16 3-pass.
// Persistent CTAs: 256 thr (8 warps, 2x4), tile M=64, N=128, K=256.
// B (hi+lo) SMEM-resident for all tiles; A staged hi/lo per tile.
// ============================================================================
#define SOFF_A_HI  0
#define SOFF_A_LO  (64 * LDA * 2)                 // 33792
#define SOFF_B     (2 * 64 * LDA * 2)             // 67584 (hi then lo, contiguous)
#define SOFF_SCALE (SOFF_B + 2 * 128 * LDB * 2)   // 202752
#define SOFF_BIAS  (SOFF_SCALE + 512)
#define GEMM_SMEM  (SOFF_BIAS + 512)

__global__ void __launch_bounds__(256, 1)
gemm_mma_kernel(int layer,
                const float* __restrict__ bias,
                const float* __restrict__ gam, const float* __restrict__ bet,
                const float* __restrict__ mean, const float* __restrict__ var,
                int n) {
    extern __shared__ char sm[];
    uint32_t sb = smem_to_u32(sm);
    int tid = threadIdx.x;
    int wid = tid >> 5;
    int lane = tid & 31;

    // Resident B: copy hi+lo image (contiguous 135168 B) into SMEM
    {
        const float4* bsrc = (const float4*)&g_Bw[layer][0][0][0];
        float4* bdst = (float4*)(sm + SOFF_B);
        for (int i = tid; i < (2 * 128 * LDB * 2) / 16; i += 256) bdst[i] = bsrc[i];
    }
    if (tid < 128) {
        float s = gam[tid] * rsqrtf(var[tid] + BN_EPS);
        *(float*)(sm + SOFF_SCALE + tid * 4) = s;
        *(float*)(sm + SOFF_BIAS + tid * 4) = (bias[tid] - mean[tid]) * s + bet[tid];
    }
    __syncthreads();

    const float* sScale = (const float*)(sm + SOFF_SCALE);
    const float* sBias = (const float*)(sm + SOFF_BIAS);
    int wm = (wid >> 2) * 32;   // warp M offset (0, 32)
    int wn = (wid & 3) * 32;    // warp N offset (0..96)
    int ntiles = (n + 63) / 64;

    for (int tile = blockIdx.x; tile < ntiles; tile += gridDim.x) {
        int rowBase = tile * 64;

        // --- Stage A (64 x 256 f32 -> hi/lo bf16 SMEM) ---
        for (int idx = tid; idx < 64 * 64; idx += 256) {
            int r = idx >> 6;
            int c4 = idx & 63;
            int grow = rowBase + r;
            float4 v = make_float4(0.f, 0.f, 0.f, 0.f);
            if (grow < n) {
                if (c4 < 32) v = ((const float4*)g_agg)[(size_t)grow * 32 + c4];
                else         v = ((const float4*)g_h)[(size_t)grow * 32 + (c4 - 32)];
            }
            unsigned long long lo;
            unsigned long long hi = split4(v, &lo);
            int k0 = c4 * 4;
            *(unsigned long long*)(sm + SOFF_A_HI + (r * LDA + k0) * 2) = hi;
            *(unsigned long long*)(sm + SOFF_A_LO + (r * LDA + k0) * 2) = lo;
        }
        __syncthreads();

        // --- Compute: 3 passes x 16 k-steps ---
        float acc[2][4][4];
        #pragma unroll
        for (int mf = 0; mf < 2; mf++)
            #pragma unroll
            for (int nf = 0; nf < 4; nf++)
                #pragma unroll
                for (int c = 0; c < 4; c++) acc[mf][nf][c] = 0.f;

        #pragma unroll
        for (int pass = 0; pass < 3; pass++) {
            uint32_t aBase = sb + ((pass == 2) ? SOFF_A_LO : SOFF_A_HI);
            uint32_t bOff = SOFF_B + ((pass == 1) ? 128 * LDB * 2 : 0);
            const __nv_bfloat16* pB = (const __nv_bfloat16*)(sm + bOff);
            #pragma unroll 4
            for (int ks = 0; ks < 16; ks++) {
                int k0 = ks * 16;
                uint32_t a[2][4];
                #pragma unroll
                for (int mf = 0; mf < 2; mf++) {
                    uint32_t addr = aBase +
                        ((wm + mf * 16 + (lane & 15)) * LDA + k0 + (lane >> 4) * 8) * 2;
                    ldmatrix_x4(a[mf], addr);
                }
                uint32_t b[4][2];
                #pragma unroll
                for (int nf = 0; nf < 4; nf++) {
                    const __nv_bfloat16* bp =
                        pB + (wn + nf * 8 + (lane >> 2)) * LDB + k0 + (lane & 3) * 2;
                    b[nf][0] = *(const uint32_t*)bp;
                    b[nf][1] = *(const uint32_t*)(bp + 8);
                }
                #pragma unroll
                for (int mf = 0; mf < 2; mf++)
                    #pragma unroll
                    for (int nf = 0; nf < 4; nf++)
                        mma_bf16(acc[mf][nf], a[mf], b[nf]);
            }
        }

        // --- Epilogue: BN + ReLU, direct register -> global (float2) ---
        #pragma unroll
        for (int mf = 0; mf < 2; mf++) {
            #pragma unroll
            for (int nf = 0; nf < 4; nf++) {
                int col = wn + nf * 8 + (lane & 3) * 2;
                float s0 = sScale[col], s1 = sScale[col + 1];
                float bb0 = sBias[col], bb1 = sBias[col + 1];
                int row0 = rowBase + wm + mf * 16 + (lane >> 2);
                if (row0 < n) {
                    float2 o;
                    o.x = fmaxf(acc[mf][nf][0] * s0 + bb0, 0.f);
                    o.y = fmaxf(acc[mf][nf][1] * s1 + bb1, 0.f);
                    *(float2*)&g_h[(size_t)row0 * 128 + col] = o;
                }
                int row1 = row0 + 8;
                if (row1 < n) {
                    float2 o;
                    o.x = fmaxf(acc[mf][nf][2] * s0 + bb0, 0.f);
                    o.y = fmaxf(acc[mf][nf][3] * s1 + bb1, 0.f);
                    *(float2*)&g_h[(size_t)row1 * 128 + col] = o;
                }
            }
        }
        __syncthreads();
    }
}

// ============================================================================
// Layer 4 (commuted)
// ============================================================================
__global__ void layer4_node_kernel(const float* __restrict__ Wl4,
                                   const float* __restrict__ Wr4,
                                   const float* __restrict__ b4,
                                   float* __restrict__ out, int n) {
    int g = blockIdx.x * blockDim.x + threadIdx.x;
    int i = g >> 5;
    int lane = g & 31;
    if (i < n) {
        float4 hv = ((const float4*)(g_h + (size_t)i * HDIM))[lane];
        float4 wl = ((const float4*)Wl4)[lane];
        float4 wr = ((const float4*)Wr4)[lane];
        float yv = hv.x * wl.x + hv.y * wl.y + hv.z * wl.z + hv.w * wl.w;
        float zv = hv.x * wr.x + hv.y * wr.y + hv.z * wr.z + hv.w * wr.w;
        #pragma unroll
        for (int o = 16; o > 0; o >>= 1) {
            yv += __shfl_xor_sync(0xFFFFFFFFu, yv, o);
            zv += __shfl_xor_sync(0xFFFFFFFFu, zv, o);
        }
        if (lane == 0) {
            g_s[i] = yv;
            out[i] = zv + b4[0];
        }
    }
}

__global__ void layer4_gather_kernel(float* __restrict__ out, int n) {
    int i = blockIdx.x * blockDim.x + threadIdx.x;
    if (i < n) {
        int b = g_rowptr[i], eend = g_rowptr[i + 1];
        float acc = 0.f;
        for (int j = b; j < eend; j++) acc += g_s[g_csr[j]];
        out[i] += acc;
    }
}

// ============================================================================
// Launch
// ============================================================================
extern "C" void kernel_launch(void* const* d_in, const int* in_sizes, int n_in,
                              void* d_out, int out_size) {
    const float* x  = (const float*)d_in[0];
    const int*   ei = (const int*)d_in[1];
    const float* Wl1 = (const float*)d_in[2];
    const float* Wr1 = (const float*)d_in[3];
    const float* b1  = (const float*)d_in[4];
    const float* Wl2 = (const float*)d_in[5];
    const float* Wr2 = (const float*)d_in[6];
    const float* b2  = (const float*)d_in[7];
    const float* Wl3 = (const float*)d_in[8];
    const float* Wr3 = (const float*)d_in[9];
    const float* b3  = (const float*)d_in[10];
    const float* Wl4 = (const float*)d_in[11];
    const float* Wr4 = (const float*)d_in[12];
    const float* b4  = (const float*)d_in[13];
    const float* g1  = (const float*)d_in[14];
    const float* be1 = (const float*)d_in[15];
    const float* m1  = (const float*)d_in[16];
    const float* v1  = (const float*)d_in[17];
    const float* g2  = (const float*)d_in[18];
    const float* be2 = (const float*)d_in[19];
    const float* m2  = (const float*)d_in[20];
    const float* v2  = (const float*)d_in[21];
    const float* g3  = (const float*)d_in[22];
    const float* be3 = (const float*)d_in[23];
    const float* m3  = (const float*)d_in[24];
    const float* v3  = (const float*)d_in[25];

    int n = in_sizes[0];
    int e = in_sizes[1] / 2;
    const int* src = ei;
    const int* dst = ei + e;
    float* out = (float*)d_out;

    cudaFuncSetAttribute(gemm_mma_kernel,
                         cudaFuncAttributeMaxDynamicSharedMemorySize, GEMM_SMEM);

    int ntiles = (n + 63) / 64;
    int gemmGrid = ntiles < 148 ? ntiles : 148;

    // --- CSR build + weight prep ---
    zero_deg_kernel<<<(n + 255) / 256, 256>>>(n);
    count_kernel<<<(e + 255) / 256, 256>>>(dst, e);
    prep_weights_kernel<<<64, 256>>>(Wl2, Wr2, Wl3, Wr3);
    scan_kernel<<<1, 1024>>>(n);
    fill_kernel<<<(e + 255) / 256, 256>>>(src, dst, e);

    // --- Layer 1 (scalar gather) ---
    gather_scalar_x_kernel<<<(n + 255) / 256, 256>>>(x, n);
    layer1_kernel<<<(n * HDIM + 255) / 256, 256>>>(x, Wl1, Wr1, b1, g1, be1, m1, v1, n);

    // --- Layer 2 ---
    gather_feat_kernel<<<(n * 32 + 255) / 256, 256>>>(n);
    gemm_mma_kernel<<<gemmGrid, 256, GEMM_SMEM>>>(0, b2, g2, be2, m2, v2, n);

    // --- Layer 3 ---
    gather_feat_kernel<<<(n * 32 + 255) / 256, 256>>>(n);
    gemm_mma_kernel<<<gemmGrid, 256, GEMM_SMEM>>>(1, b3, g3, be3, m3, v3, n);

    // --- Layer 4 ---
    layer4_node_kernel<<<(n * 32 + 255) / 256, 256>>>(Wl4, Wr4, b4, out, n);
    layer4_gather_kernel<<<(n + 255) / 256, 256>>>(out, n);
}